// round 9
// baseline (speedup 1.0000x reference)
#include <cuda_runtime.h>
#include <cuda_bf16.h>
#include <cstdint>

// y = x @ w + b  (exact collapse of the memristor model; G_off / K_V / k_g all
// cancel).  3-term bf16-split GEMM on legacy mma.sync tensor cores:
//   y ~= xh@wh + xl@wh + xh@wl   (fp32 accum, rel err ~2^-16)
// Single fused kernel, 256 CTAs x 512 thr = 8 col-tiles x 32 k-chunks,
// 2 CTAs per SM (all 256 co-resident -> spin barrier safe, stalls interleave):
//   phase 1: per-CTA 128x64x32 HMMA GEMM (16 warps, warp = 16 rows x 32 cols)
//   release/acquire grid barrier   phase 2: coalesced 2-half reduce + bias.

#define NIN 1024
#define NOUT 512
#define BATCH 128
#define KCHUNKS 32
#define KCHUNK 32
#define CTILE 64
#define NTHR 512
#define NCTA 256

#define ASTRIDE 72            // bf16 row stride (144 B) -> conflict-free frags
#define A_ROWS 128
#define B_ROWS 64

#define OFF_AHI 0
#define OFF_ALO (OFF_AHI + A_ROWS * ASTRIDE)
#define OFF_BHI (OFF_ALO + A_ROWS * ASTRIDE)
#define OFF_BLO (OFF_BHI + B_ROWS * ASTRIDE)
#define SMEM_ELEMS (OFF_BLO + B_ROWS * ASTRIDE)
#define SMEM_BYTES (SMEM_ELEMS * 2)          // 55296 B -> 2 CTAs/SM

__device__ float g_partial[KCHUNKS * BATCH * NOUT];   // 8 MB scratch
__device__ unsigned g_bar;                            // monotonic ticket

__device__ __forceinline__ uint32_t packbf(float a, float b) {
    __nv_bfloat162 h = __floats2bfloat162_rn(a, b);   // a -> low 16 bits
    return *reinterpret_cast<uint32_t*>(&h);
}
__device__ __forceinline__ uint64_t pack64(uint32_t lo, uint32_t hi) {
    uint64_t r; asm("mov.b64 %0, {%1, %2};" : "=l"(r) : "r"(lo), "r"(hi)); return r;
}
__device__ __forceinline__ void mma_bf16(float* c, const uint32_t* a, const uint32_t* b) {
    asm volatile(
        "mma.sync.aligned.m16n8k16.row.col.f32.bf16.bf16.f32 "
        "{%0,%1,%2,%3}, {%4,%5,%6,%7}, {%8,%9}, {%0,%1,%2,%3};"
        : "+f"(c[0]), "+f"(c[1]), "+f"(c[2]), "+f"(c[3])
        : "r"(a[0]), "r"(a[1]), "r"(a[2]), "r"(a[3]), "r"(b[0]), "r"(b[1]));
}

__global__ __launch_bounds__(NTHR, 2) void fused_kernel(
    const float* __restrict__ X, const float* __restrict__ W,
    const float* __restrict__ B, float* __restrict__ out)
{
    extern __shared__ __nv_bfloat16 sm[];
    __nv_bfloat16* Ahi = sm + OFF_AHI;
    __nv_bfloat16* Alo = sm + OFF_ALO;
    __nv_bfloat16* Bhi = sm + OFF_BHI;
    __nv_bfloat16* Blo = sm + OFF_BLO;

    const int t = threadIdx.x, bid = blockIdx.x;
    const int warp = t >> 5, lane = t & 31;
    const int g  = lane >> 2;          // group row 0..7
    const int tq = lane & 3;           // thread-in-group 0..3
    const int c0  = (bid & 7) * CTILE;        // col tile 0..7
    const int kc0 = (bid >> 3) * KCHUNK;      // k-chunk 0..31

    // ---- fill A: X[128 rows x 32 k] -> hi/lo bf16.  128*8 float4 = 1024 slots
    //      = exactly 2 iterations of 512 threads. ----
    #pragma unroll
    for (int i = 0; i < 2; ++i) {
        int idx = t + i * NTHR;                // 0..1023
        int kq = idx & 7, row = idx >> 3;      // row 0..127, kq 0..7
        float4 xv = *reinterpret_cast<const float4*>(&X[row * NIN + kc0 + 4 * kq]);
        float h0 = __bfloat162float(__float2bfloat16(xv.x));
        float h1 = __bfloat162float(__float2bfloat16(xv.y));
        float h2 = __bfloat162float(__float2bfloat16(xv.z));
        float h3 = __bfloat162float(__float2bfloat16(xv.w));
        int e = row * ASTRIDE + 4 * kq;        // 144*row + 8*kq bytes: 8B-aligned
        *reinterpret_cast<uint64_t*>(&Ahi[e]) = pack64(packbf(h0, h1), packbf(h2, h3));
        *reinterpret_cast<uint64_t*>(&Alo[e]) =
            pack64(packbf(xv.x - h0, xv.y - h1), packbf(xv.z - h2, xv.w - h3));
    }
    // ---- fill B: W[32k x 64n] -> [n][k] hi/lo bf16 pairs. 64n*16kp = 1024. ----
    #pragma unroll
    for (int i = 0; i < 2; ++i) {
        int idx = t + i * NTHR;                // 0..1023
        int n = idx & 63, kp = idx >> 6;       // kp 0..15; lanes consecutive n
        float w0 = W[(kc0 + 2 * kp) * NOUT + c0 + n];
        float w1 = W[(kc0 + 2 * kp + 1) * NOUT + c0 + n];
        float h0 = __bfloat162float(__float2bfloat16(w0));
        float h1 = __bfloat162float(__float2bfloat16(w1));
        *reinterpret_cast<uint32_t*>(&Bhi[n * ASTRIDE + 2 * kp]) = packbf(h0, h1);
        *reinterpret_cast<uint32_t*>(&Blo[n * ASTRIDE + 2 * kp]) = packbf(w0 - h0, w1 - h1);
    }
    __syncthreads();

    // ---- phase 1 compute: warp = rows 16*(w>>1).., cols 32*(w&1).. ----
    float acc[4][4];
    #pragma unroll
    for (int j = 0; j < 4; ++j)
        #pragma unroll
        for (int q = 0; q < 4; ++q) acc[j][q] = 0.f;

    const int wr  = warp >> 1;
    const int cn0 = (warp & 1) * 32;
    const int arow0 = (wr * 16 + g) * ASTRIDE;
    const int arow1 = arow0 + 8 * ASTRIDE;

    #pragma unroll
    for (int kk = 0; kk < 2; ++kk) {
        const int kb = kk * 16 + 2 * tq;       // 0..30; +8 stays < 32 (k-span 32)
        uint32_t ah[4], al[4];
        ah[0] = *reinterpret_cast<const uint32_t*>(&Ahi[arow0 + kb]);
        ah[1] = *reinterpret_cast<const uint32_t*>(&Ahi[arow1 + kb]);
        ah[2] = *reinterpret_cast<const uint32_t*>(&Ahi[arow0 + kb + 8]);
        ah[3] = *reinterpret_cast<const uint32_t*>(&Ahi[arow1 + kb + 8]);
        al[0] = *reinterpret_cast<const uint32_t*>(&Alo[arow0 + kb]);
        al[1] = *reinterpret_cast<const uint32_t*>(&Alo[arow1 + kb]);
        al[2] = *reinterpret_cast<const uint32_t*>(&Alo[arow0 + kb + 8]);
        al[3] = *reinterpret_cast<const uint32_t*>(&Alo[arow1 + kb + 8]);

        uint32_t bh[4][2], bl[4][2];
        #pragma unroll
        for (int j = 0; j < 4; ++j) {
            const int brow = (cn0 + 8 * j + g) * ASTRIDE;
            bh[j][0] = *reinterpret_cast<const uint32_t*>(&Bhi[brow + kb]);
            bh[j][1] = *reinterpret_cast<const uint32_t*>(&Bhi[brow + kb + 8]);
            bl[j][0] = *reinterpret_cast<const uint32_t*>(&Blo[brow + kb]);
            bl[j][1] = *reinterpret_cast<const uint32_t*>(&Blo[brow + kb + 8]);
        }
        #pragma unroll
        for (int j = 0; j < 4; ++j) mma_bf16(acc[j], ah, bh[j]);
        #pragma unroll
        for (int j = 0; j < 4; ++j) mma_bf16(acc[j], al, bh[j]);
        #pragma unroll
        for (int j = 0; j < 4; ++j) mma_bf16(acc[j], ah, bl[j]);
    }

    // ---- store partials ----
    {
        float* part = g_partial + (bid >> 3) * (BATCH * NOUT);
        const int r0 = wr * 16 + g;
        #pragma unroll
        for (int j = 0; j < 4; ++j) {
            const int col = c0 + cn0 + 8 * j + 2 * tq;
            *reinterpret_cast<float2*>(&part[r0 * NOUT + col])       = make_float2(acc[j][0], acc[j][1]);
            *reinterpret_cast<float2*>(&part[(r0 + 8) * NOUT + col]) = make_float2(acc[j][2], acc[j][3]);
        }
    }

    // ---- grid barrier: release/acquire ticket (256 co-resident CTAs) ----
    __syncthreads();
    if (t == 0) {
        unsigned my;
        asm volatile("atom.add.release.gpu.global.u32 %0, [%1], 1;"
                     : "=r"(my) : "l"(&g_bar) : "memory");
        unsigned target = (my & ~(NCTA - 1u)) + NCTA;
        unsigned cur;
        do {
            asm volatile("ld.acquire.gpu.global.u32 %0, [%1];"
                         : "=r"(cur) : "l"(&g_bar) : "memory");
        } while ((int)(cur - target) < 0);
    }
    __syncthreads();

    // ---- phase 2: each CTA reduces 256 outputs; half-threads per 16 partials,
    //      combine through smem (fixed order -> deterministic) ----
    {
        float* red = reinterpret_cast<float*>(sm);     // reuse tile smem
        int o   = bid * 256 + (t & 255);               // 0..65535
        int hset = t >> 8;                             // 0: partials 0-15, 1: 16-31
        float v[16];
        #pragma unroll
        for (int c = 0; c < 16; ++c)
            v[c] = g_partial[(hset * 16 + c) * (BATCH * NOUT) + o];
        #pragma unroll
        for (int s = 1; s < 16; s <<= 1)
            #pragma unroll
            for (int c = 0; c < 16; c += 2 * s)
                v[c] += v[c + s];
        if (hset) red[t & 255] = v[0];
        __syncthreads();
        if (!hset)
            out[o] = (v[0] + red[t]) + B[o & (NOUT - 1)];
    }
}

extern "C" void kernel_launch(void* const* d_in, const int* in_sizes, int n_in,
                              void* d_out, int out_size)
{
    const float* X = (const float*)d_in[0];  // (128, 1024)
    const float* W = (const float*)d_in[1];  // (1024, 512)
    const float* B = (const float*)d_in[2];  // (512,)
    float* out = (float*)d_out;              // (128, 512)

    cudaFuncSetAttribute(fused_kernel, cudaFuncAttributeMaxDynamicSharedMemorySize, SMEM_BYTES);
    fused_kernel<<<NCTA, NTHR, SMEM_BYTES>>>(X, W, B, out);
}